// round 10
// baseline (speedup 1.0000x reference)
#include <cuda_runtime.h>

#define NODES 2048
#define EDGES 65536
#define D     128
#define NB    32          // nodes per precompute tile
#define CAP   128         // bucket capacity per target (in-degree ~Poisson(32))
#define EPSF  1e-6f

// ---------------- scratch (no allocation; zero-initialized at module load) ----------------
__device__ int   g_cursor[NODES];             // per-target count (reset by k_agg each replay)
__device__ int   g_bucket[NODES * CAP];       // src ids grouped by target
__device__ __align__(16) float g_P[NODES * D];   // x @ fW[:128,:]
__device__ __align__(16) float g_Q[NODES * D];   // x @ fW[128:,:]
__device__ float g_es[NODES];                 // exp(s[n]),  s = x@wW[:128]
__device__ float g_et[NODES];                 // exp(t[n]),  t = x@wW[128:]

// ---------------- kernel 1: 32-node-tile GEMM (8 nodes/thread) + es,et + scatter -----------
// 256 blocks: grp = node group (0..63, 32 nodes), v = variant (P/Q x column half).
// Dynamic smem: 128x64 fW slice (32KB). Static ~19.5KB -> combined >48KB: needs attr opt-in.
extern __shared__ float s_w[];   // [D * 64]

__global__ __launch_bounds__(256) void k_pre(const float* __restrict__ x,
                                             const float* __restrict__ fW,
                                             const float* __restrict__ wW,
                                             const int* __restrict__ src,
                                             const int* __restrict__ tgt) {
    __shared__ float xs[D][NB + 2];   // k-major x tile (34-float rows: 8B-aligned)
    __shared__ float wWs[2 * D];
    __shared__ float red[256];
    int tid = threadIdx.x;
    int v   = blockIdx.x & 3;
    int isQ = v & 1;
    int jh  = v >> 1;
    int grp = blockIdx.x >> 2;
    int nb  = grp * NB;

    // direct scatter: 256 edges per block (1/thread), hidden behind staging
    {
        int e = blockIdx.x * 256 + tid;
        int t = tgt[e];
        int pos = atomicAdd(&g_cursor[t], 1);
        if (pos < CAP) g_bucket[t * CAP + pos] = src[e];
    }

    // stage fW slice [128 x 64] (32KB, 8 float4/thread), x tile (17KB), wW
    {
        const float* base = fW + (isQ ? D * D : 0) + jh * 64;
        float4*      d4   = reinterpret_cast<float4*>(s_w);
#pragma unroll
        for (int r = 0; r < 8; r++) {
            int idx = tid + r * 256;          // 0..2047 float4
            int row = idx >> 4, c4 = idx & 15;
            d4[idx] = *reinterpret_cast<const float4*>(base + row * D + c4 * 4);
        }
    }
    for (int i = tid; i < NB * D; i += 256) {
        int n = i >> 7, k = i & 127;
        xs[k][n] = x[(nb + n) * D + k];
    }
    wWs[tid] = wW[tid];
    __syncthreads();

    // each thread: column j (of 64), 8 nodes, 4 packed f32x2 accumulators
    int j = tid & 63, g = tid >> 6;
    int xbase = g * 8;
    const float* sw = s_w + j;
    unsigned long long a0 = 0, a1 = 0, a2 = 0, a3 = 0;

#pragma unroll 8
    for (int k = 0; k < D; k++) {
        float w = sw[k * 64];
        unsigned long long ww;
        asm("mov.b64 %0,{%1,%1};" : "=l"(ww) : "f"(w));
        const unsigned long long* xr =
            reinterpret_cast<const unsigned long long*>(&xs[k][xbase]);
        unsigned long long x0 = xr[0], x1 = xr[1], x2 = xr[2], x3 = xr[3];
        asm("fma.rn.f32x2 %0,%1,%2,%0;" : "+l"(a0) : "l"(x0), "l"(ww));
        asm("fma.rn.f32x2 %0,%1,%2,%0;" : "+l"(a1) : "l"(x1), "l"(ww));
        asm("fma.rn.f32x2 %0,%1,%2,%0;" : "+l"(a2) : "l"(x2), "l"(ww));
        asm("fma.rn.f32x2 %0,%1,%2,%0;" : "+l"(a3) : "l"(x3), "l"(ww));
    }

    float* dst = (isQ ? g_Q : g_P) + jh * 64;
    float lo, hi;
#define STORE_PAIR(acc, i) \
    asm("mov.b64 {%0,%1},%2;" : "=f"(lo), "=f"(hi) : "l"(acc)); \
    dst[(nb + xbase + 2*(i)    ) * D + j] = lo; \
    dst[(nb + xbase + 2*(i) + 1) * D + j] = hi;
    STORE_PAIR(a0, 0) STORE_PAIR(a1, 1) STORE_PAIR(a2, 2) STORE_PAIR(a3, 3)
#undef STORE_PAIR

    // s,t + exp: one writer per node group (v == 0 blocks), 32 nodes
    if (v == 0) {
        {
            int n = tid & 31, half = (tid >> 5) & 1, q = tid >> 6;
            const float* wv = wWs + half * D;
            float p = 0.f;
#pragma unroll 8
            for (int k = q * 32; k < q * 32 + 32; k++) p = fmaf(xs[k][n], wv[k], p);
            red[tid] = p;
        }
        __syncthreads();
        if (tid < 64) {
            float s4 = red[tid] + red[tid + 64] + red[tid + 128] + red[tid + 192];
            float ev = __expf(s4);
            int n = tid & 31, half = tid >> 5;
            if (half) g_et[nb + n] = ev; else g_es[nb + n] = ev;
        }
    }
}

// ---------------- kernel 2: block-per-node aggregation, batch-8 deep gathers ---------------
__global__ __launch_bounds__(128) void k_agg(float* __restrict__ out,
                                             const float* __restrict__ fb) {
    __shared__ float4 sacc[4][32];
    __shared__ float  sasum[4];
    int n = blockIdx.x, tid = threadIdx.x, lane = tid & 31, wid = tid >> 5;

    int cnt = min(g_cursor[n], CAP);
    const int* bk = &g_bucket[n * CAP];

    float4 q4 = *reinterpret_cast<const float4*>(&g_Q[n * D + lane * 4]);
    float4 f4 = *reinterpret_cast<const float4*>(&fb[lane * 4]);
    float4 qf = make_float4(q4.x + f4.x, q4.y + f4.y, q4.z + f4.z, q4.w + f4.w);

    // contiguous per-warp chunk (typically ~8 edges -> one batch-8 deep gather)
    int chunk = (cnt + 3) >> 2;
    int b0 = min(wid * chunk, cnt);
    int e0 = min(b0 + chunk, cnt);

    float4 acc = make_float4(0.f, 0.f, 0.f, 0.f);
    float asum = 0.f;

    int i = b0;
    for (; i + 8 <= e0; i += 8) {
        int   sid[8];
        float w[8];
#pragma unroll
        for (int u = 0; u < 8; u++) sid[u] = __ldg(bk + i + u);   // independent, MLP 8
#pragma unroll
        for (int u = 0; u < 8; u++) w[u] = g_es[sid[u]];          // one dep hop, MLP 8
#pragma unroll
        for (int u = 0; u < 8; u++) {
            float4 p = *reinterpret_cast<const float4*>(&g_P[sid[u] * D + lane * 4]);
            acc.x = fmaf(fmaxf(p.x + qf.x, 0.f), w[u], acc.x);
            acc.y = fmaf(fmaxf(p.y + qf.y, 0.f), w[u], acc.y);
            acc.z = fmaf(fmaxf(p.z + qf.z, 0.f), w[u], acc.z);
            acc.w = fmaf(fmaxf(p.w + qf.w, 0.f), w[u], acc.w);
            asum += w[u];
        }
    }
    for (; i < e0; i++) {
        int   sid = __ldg(bk + i);
        float w   = g_es[sid];
        float4 p  = *reinterpret_cast<const float4*>(&g_P[sid * D + lane * 4]);
        acc.x = fmaf(fmaxf(p.x + qf.x, 0.f), w, acc.x);
        acc.y = fmaf(fmaxf(p.y + qf.y, 0.f), w, acc.y);
        acc.z = fmaf(fmaxf(p.z + qf.z, 0.f), w, acc.z);
        acc.w = fmaf(fmaxf(p.w + qf.w, 0.f), w, acc.w);
        asum += w;
    }

    sacc[wid][lane] = acc;
    if (lane == 0) sasum[wid] = asum;
    __syncthreads();
    if (tid == 0) g_cursor[n] = 0;   // reset for next replay (all reads done)

    const float* sp = reinterpret_cast<const float*>(sacc);
    float a = sp[tid] + sp[128 + tid] + sp[256 + tid] + sp[384 + tid];
    float s = sasum[0] + sasum[1] + sasum[2] + sasum[3];
    float et = g_et[n];
    out[n * D + tid] = (et * a) / (et * s + EPSF);   // exp(s+t)=es*et; EPS outside
}

// ---------------- launch: two graph nodes ----------------
extern "C" void kernel_launch(void* const* d_in, const int* in_sizes, int n_in,
                              void* d_out, int out_size) {
    const float* x   = (const float*)d_in[0];
    const int*   src = (const int*)  d_in[2];
    const int*   tgt = (const int*)  d_in[3];
    const float* fW  = (const float*)d_in[6];
    const float* fb  = (const float*)d_in[7];
    const float* wW  = (const float*)d_in[8];
    float*       out = (float*)d_out;

    // combined static+dynamic smem of k_pre exceeds 48KB -> explicit opt-in
    // (host-side attribute set, one-time; same pattern as the R6 passing kernel)
    static bool attr_done = false;
    if (!attr_done) {
        cudaFuncSetAttribute(k_pre, cudaFuncAttributeMaxDynamicSharedMemorySize,
                             64 * 1024);
        attr_done = true;
    }

    k_pre<<<256, 256, D * 64 * sizeof(float)>>>(x, fW, wW, src, tgt);
    k_agg<<<NODES, 128>>>(out, fb);
}

// round 12
// speedup vs baseline: 1.0184x; 1.0184x over previous
#include <cuda_runtime.h>

#define NODES 2048
#define EDGES 65536
#define D     128
#define NB    16          // nodes per precompute tile
#define CAP   128         // bucket capacity per target (in-degree ~Poisson(32))
#define EPSF  1e-6f

// ---------------- scratch (no allocation; zero-initialized at module load) ----------------
__device__ int   g_cursor[NODES];             // per-target count (reset by k_agg each replay)
__device__ int   g_bucket[NODES * CAP];       // src ids grouped by target
__device__ __align__(16) float g_P[NODES * D];   // x @ fW[:128,:]
__device__ __align__(16) float g_Q[NODES * D];   // x @ fW[128:,:]
__device__ float g_es[NODES];                 // exp(s[n]),  s = x@wW[:128]
__device__ float g_et[NODES];                 // exp(t[n]),  t = x@wW[128:]

// ---------------- kernel 1: split P/Q GEMM (half of fW in smem) + es,et + scatter ----------
// Blocks 0..127 compute P (fW[:128]); blocks 128..255 compute Q (fW[128:]).
// 64KB dynamic smem + ~11KB static -> 2 resident blocks/SM. (R7-measured best config.)
extern __shared__ float s_w[];   // [D*D] = one half of fW

__global__ __launch_bounds__(256) void k_pre(const float* __restrict__ x,
                                             const float* __restrict__ fW,
                                             const float* __restrict__ wW,
                                             const int* __restrict__ src,
                                             const int* __restrict__ tgt) {
    __shared__ float xs[D][NB + 2];   // k-major x tile, padded (8B-aligned rows)
    __shared__ float wWs[2 * D];
    __shared__ float red[128];
    int tid = threadIdx.x;
    int isQ = (blockIdx.x >= 128);
    int blk = blockIdx.x & 127;
    int nb  = blk * NB;

    // direct scatter: 256 edges per block (1/thread), hidden behind the staging
    {
        int e = blockIdx.x * 256 + tid;
        int t = tgt[e];
        int pos = atomicAdd(&g_cursor[t], 1);
        if (pos < CAP) g_bucket[t * CAP + pos] = src[e];
    }

    // stage this variant's half of fW (64KB, 16 float4/thread), x tile, wW
    {
        const float4* s4 = reinterpret_cast<const float4*>(fW + (isQ ? D * D : 0));
        float4*       d4 = reinterpret_cast<float4*>(s_w);
#pragma unroll
        for (int r = 0; r < (D * D / 4) / 256; r++)
            d4[tid + r * 256] = s4[tid + r * 256];
    }
    for (int i = tid; i < NB * D; i += 256) {
        int n = i >> 7, k = i & 127;
        xs[k][n] = x[(nb + n) * D + k];
    }
    wWs[tid] = wW[tid];
    __syncthreads();

    // each thread: output column j, 8 nodes, 4 packed f32x2 accumulators
    int j = tid & 127, g = tid >> 7;
    int xbase = g * 8;
    const float* sw = s_w + j;
    unsigned long long a0 = 0, a1 = 0, a2 = 0, a3 = 0;

#pragma unroll 8
    for (int k = 0; k < D; k++) {
        float w = sw[k * D];
        unsigned long long ww;
        asm("mov.b64 %0,{%1,%1};" : "=l"(ww) : "f"(w));
        const unsigned long long* xr =
            reinterpret_cast<const unsigned long long*>(&xs[k][xbase]);
        unsigned long long x0 = xr[0], x1 = xr[1], x2 = xr[2], x3 = xr[3];
        asm("fma.rn.f32x2 %0,%1,%2,%0;" : "+l"(a0) : "l"(x0), "l"(ww));
        asm("fma.rn.f32x2 %0,%1,%2,%0;" : "+l"(a1) : "l"(x1), "l"(ww));
        asm("fma.rn.f32x2 %0,%1,%2,%0;" : "+l"(a2) : "l"(x2), "l"(ww));
        asm("fma.rn.f32x2 %0,%1,%2,%0;" : "+l"(a3) : "l"(x3), "l"(ww));
    }

    float* dst = isQ ? g_Q : g_P;
    float lo, hi;
#define STORE_PAIR(acc, i) \
    asm("mov.b64 {%0,%1},%2;" : "=f"(lo), "=f"(hi) : "l"(acc)); \
    dst[(nb + xbase + 2*(i)    ) * D + j] = lo; \
    dst[(nb + xbase + 2*(i) + 1) * D + j] = hi;
    STORE_PAIR(a0, 0) STORE_PAIR(a1, 1) STORE_PAIR(a2, 2) STORE_PAIR(a3, 3)
#undef STORE_PAIR

    // s,t + exp: only in P-variant blocks (one writer per node)
    if (!isQ) {
        if (tid < 128) {
            int n = tid & 15, half = (tid >> 4) & 1, q = tid >> 5;
            const float* wv = wWs + half * D;
            float p = 0.f;
#pragma unroll 8
            for (int k = q * 32; k < q * 32 + 32; k++) p = fmaf(xs[k][n], wv[k], p);
            red[tid] = p;
        }
        __syncthreads();
        if (tid < 32) {
            float v = red[tid] + red[tid + 32] + red[tid + 64] + red[tid + 96];
            float ev = __expf(v);
            int n = tid & 15, half = tid >> 4;
            if (half) g_et[nb + n] = ev; else g_es[nb + n] = ev;
        }
    }
}

// ---------------- kernel 2: block-per-node aggregation, batch-8 deep gathers ---------------
__global__ __launch_bounds__(128) void k_agg(float* __restrict__ out,
                                             const float* __restrict__ fb) {
    __shared__ float4 sacc[4][32];
    __shared__ float  sasum[4];
    int n = blockIdx.x, tid = threadIdx.x, lane = tid & 31, wid = tid >> 5;

    int cnt = min(g_cursor[n], CAP);
    const int* bk = &g_bucket[n * CAP];

    float4 q4 = *reinterpret_cast<const float4*>(&g_Q[n * D + lane * 4]);
    float4 f4 = *reinterpret_cast<const float4*>(&fb[lane * 4]);
    float4 qf = make_float4(q4.x + f4.x, q4.y + f4.y, q4.z + f4.z, q4.w + f4.w);

    // contiguous per-warp chunk (typically ~8 edges -> one batch-8 deep gather)
    int chunk = (cnt + 3) >> 2;
    int b0 = min(wid * chunk, cnt);
    int e0 = min(b0 + chunk, cnt);

    float4 acc = make_float4(0.f, 0.f, 0.f, 0.f);
    float asum = 0.f;

    int i = b0;
    for (; i + 8 <= e0; i += 8) {
        int   sid[8];
        float w[8];
#pragma unroll
        for (int u = 0; u < 8; u++) sid[u] = __ldg(bk + i + u);   // independent, MLP 8
#pragma unroll
        for (int u = 0; u < 8; u++) w[u] = g_es[sid[u]];          // one dep hop, MLP 8
#pragma unroll
        for (int u = 0; u < 8; u++) {
            float4 p = *reinterpret_cast<const float4*>(&g_P[sid[u] * D + lane * 4]);
            acc.x = fmaf(fmaxf(p.x + qf.x, 0.f), w[u], acc.x);
            acc.y = fmaf(fmaxf(p.y + qf.y, 0.f), w[u], acc.y);
            acc.z = fmaf(fmaxf(p.z + qf.z, 0.f), w[u], acc.z);
            acc.w = fmaf(fmaxf(p.w + qf.w, 0.f), w[u], acc.w);
            asum += w[u];
        }
    }
    for (; i < e0; i++) {
        int   sid = __ldg(bk + i);
        float w   = g_es[sid];
        float4 p  = *reinterpret_cast<const float4*>(&g_P[sid * D + lane * 4]);
        acc.x = fmaf(fmaxf(p.x + qf.x, 0.f), w, acc.x);
        acc.y = fmaf(fmaxf(p.y + qf.y, 0.f), w, acc.y);
        acc.z = fmaf(fmaxf(p.z + qf.z, 0.f), w, acc.z);
        acc.w = fmaf(fmaxf(p.w + qf.w, 0.f), w, acc.w);
        asum += w;
    }

    sacc[wid][lane] = acc;
    if (lane == 0) sasum[wid] = asum;
    __syncthreads();
    if (tid == 0) g_cursor[n] = 0;   // reset for next replay (all reads done)

    const float* sp = reinterpret_cast<const float*>(sacc);
    float a = sp[tid] + sp[128 + tid] + sp[256 + tid] + sp[384 + tid];
    float s = sasum[0] + sasum[1] + sasum[2] + sasum[3];
    float et = g_et[n];
    out[n * D + tid] = (et * a) / (et * s + EPSF);   // exp(s+t)=es*et; EPS outside
}

// ---------------- launch: two graph nodes ----------------
extern "C" void kernel_launch(void* const* d_in, const int* in_sizes, int n_in,
                              void* d_out, int out_size) {
    const float* x   = (const float*)d_in[0];
    const int*   src = (const int*)  d_in[2];
    const int*   tgt = (const int*)  d_in[3];
    const float* fW  = (const float*)d_in[6];
    const float* fb  = (const float*)d_in[7];
    const float* wW  = (const float*)d_in[8];
    float*       out = (float*)d_out;

    // k_pre uses 64KB dynamic smem (+ ~11KB static) -> explicit opt-in required
    static bool attr_done = false;
    if (!attr_done) {
        cudaFuncSetAttribute(k_pre, cudaFuncAttributeMaxDynamicSharedMemorySize,
                             D * D * (int)sizeof(float));
        attr_done = true;
    }

    k_pre<<<256, 256, D * D * sizeof(float)>>>(x, fW, wW, src, tgt);
    k_agg<<<NODES, 128>>>(out, fb);
}

// round 13
// speedup vs baseline: 1.0861x; 1.0665x over previous
#include <cuda_runtime.h>

#define NODES 2048
#define EDGES 65536
#define D     128
#define NB    16          // nodes per precompute tile
#define CAP   128         // bucket capacity per target (in-degree ~Poisson(32))
#define EPSF  1e-6f

// ---------------- scratch (no allocation; zero-initialized at module load) ----------------
__device__ int   g_cursor[NODES];             // per-target count (reset by k_agg each replay)
__device__ int   g_bucket[NODES * CAP];       // src ids grouped by target
__device__ __align__(16) float g_P[NODES * D];   // x @ fW[:128,:]
__device__ __align__(16) float g_Q[NODES * D];   // x @ fW[128:,:]
__device__ float g_es[NODES];                 // exp(s[n]),  s = x@wW[:128]
__device__ float g_et[NODES];                 // exp(t[n]),  t = x@wW[128:]

#define CP_ASYNC16(dst_u32, src_ptr) \
    asm volatile("cp.async.cg.shared.global [%0], [%1], 16;" \
                 :: "r"(dst_u32), "l"(src_ptr))
#define CP_COMMIT() asm volatile("cp.async.commit_group;")
#define CP_WAIT(n)  asm volatile("cp.async.wait_group %0;" :: "n"(n))

// ---------------- kernel 1: split P/Q GEMM, cp.async-pipelined fW staging ------------------
// Blocks 0..127 compute P (fW[:128]); 128..255 compute Q (fW[128:]).
// fW half staged as 4 x 16KB cp.async groups; chunk c+1 loads under chunk c's FFMAs.
extern __shared__ float s_w[];   // [D*D] = one half of fW

__global__ __launch_bounds__(256) void k_pre(const float* __restrict__ x,
                                             const float* __restrict__ fW,
                                             const float* __restrict__ wW,
                                             const int* __restrict__ src,
                                             const int* __restrict__ tgt) {
    __shared__ float xs[D][NB + 2];   // k-major x tile, padded (8B-aligned rows)
    __shared__ float wWs[2 * D];
    __shared__ float red[128];
    int tid = threadIdx.x;
    int isQ = (blockIdx.x >= 128);
    int blk = blockIdx.x & 127;
    int nb  = blk * NB;

    // kick off the 4 fW chunk copies FIRST (async, 4 x 16KB commit groups)
    {
        const float* base = fW + (isQ ? D * D : 0);
        unsigned swaddr = (unsigned)__cvta_generic_to_shared(s_w);
#pragma unroll
        for (int c = 0; c < 4; c++) {
#pragma unroll
            for (int r = 0; r < 4; r++) {
                int idx = c * 1024 + tid + r * 256;      // float4 index
                CP_ASYNC16(swaddr + idx * 16, base + idx * 4);
            }
            CP_COMMIT();
        }
    }

    // direct scatter: 256 edges per block (1/thread), overlaps the async copies
    {
        int e = blockIdx.x * 256 + tid;
        int t = tgt[e];
        int pos = atomicAdd(&g_cursor[t], 1);
        if (pos < CAP) g_bucket[t * CAP + pos] = src[e];
    }

    // x tile (transposed) + wW via normal ld/st (completes before first barrier)
    for (int i = tid; i < NB * D; i += 256) {
        int n = i >> 7, k = i & 127;
        xs[k][n] = x[(nb + n) * D + k];
    }
    wWs[tid] = wW[tid];

    // each thread: output column j, 8 nodes, 4 packed f32x2 accumulators
    int j = tid & 127, g = tid >> 7;
    int xbase = g * 8;
    const float* sw = s_w + j;
    unsigned long long a0 = 0, a1 = 0, a2 = 0, a3 = 0;

#define GEMM_CHUNK(C)                                                          \
    {                                                                          \
        CP_WAIT(3 - (C));                                                      \
        __syncthreads();                                                       \
        _Pragma("unroll 8")                                                    \
        for (int k = (C) * 32; k < (C) * 32 + 32; k++) {                       \
            float w = sw[k * D];                                               \
            unsigned long long ww;                                             \
            asm("mov.b64 %0,{%1,%1};" : "=l"(ww) : "f"(w));                    \
            const unsigned long long* xr =                                     \
                reinterpret_cast<const unsigned long long*>(&xs[k][xbase]);    \
            unsigned long long x0 = xr[0], x1 = xr[1], x2 = xr[2], x3 = xr[3]; \
            asm("fma.rn.f32x2 %0,%1,%2,%0;" : "+l"(a0) : "l"(x0), "l"(ww));    \
            asm("fma.rn.f32x2 %0,%1,%2,%0;" : "+l"(a1) : "l"(x1), "l"(ww));    \
            asm("fma.rn.f32x2 %0,%1,%2,%0;" : "+l"(a2) : "l"(x2), "l"(ww));    \
            asm("fma.rn.f32x2 %0,%1,%2,%0;" : "+l"(a3) : "l"(x3), "l"(ww));    \
        }                                                                      \
    }
    GEMM_CHUNK(0) GEMM_CHUNK(1) GEMM_CHUNK(2) GEMM_CHUNK(3)
#undef GEMM_CHUNK

    float* dst = isQ ? g_Q : g_P;
    float lo, hi;
#define STORE_PAIR(acc, i) \
    asm("mov.b64 {%0,%1},%2;" : "=f"(lo), "=f"(hi) : "l"(acc)); \
    dst[(nb + xbase + 2*(i)    ) * D + j] = lo; \
    dst[(nb + xbase + 2*(i) + 1) * D + j] = hi;
    STORE_PAIR(a0, 0) STORE_PAIR(a1, 1) STORE_PAIR(a2, 2) STORE_PAIR(a3, 3)
#undef STORE_PAIR

    // s,t + exp: only in P-variant blocks (one writer per node)
    if (!isQ) {
        if (tid < 128) {
            int n = tid & 15, half = (tid >> 4) & 1, q = tid >> 5;
            const float* wv = wWs + half * D;
            float p = 0.f;
#pragma unroll 8
            for (int k = q * 32; k < q * 32 + 32; k++) p = fmaf(xs[k][n], wv[k], p);
            red[tid] = p;
        }
        __syncthreads();
        if (tid < 32) {
            float v = red[tid] + red[tid + 32] + red[tid + 64] + red[tid + 96];
            float ev = __expf(v);
            int n = tid & 15, half = tid >> 4;
            if (half) g_et[nb + n] = ev; else g_es[nb + n] = ev;
        }
    }
}

// ---------------- kernel 2: 2 nodes/block aggregation, batch-8 deep gathers ----------------
__global__ __launch_bounds__(256) void k_agg(float* __restrict__ out,
                                             const float* __restrict__ fb) {
    __shared__ float4 sacc[2][4][32];
    __shared__ float  sasum[2][4];
    int tid  = threadIdx.x;
    int half = tid >> 7;            // which of the 2 nodes
    int t    = tid & 127;
    int lane = t & 31, wid = t >> 5;
    int n    = blockIdx.x * 2 + half;

    int cnt = min(g_cursor[n], CAP);
    const int* bk = &g_bucket[n * CAP];

    float4 q4 = *reinterpret_cast<const float4*>(&g_Q[n * D + lane * 4]);
    float4 f4 = *reinterpret_cast<const float4*>(&fb[lane * 4]);
    float4 qf = make_float4(q4.x + f4.x, q4.y + f4.y, q4.z + f4.z, q4.w + f4.w);

    // contiguous per-warp chunk (typically ~8 edges -> one batch-8 deep gather)
    int chunk = (cnt + 3) >> 2;
    int b0 = min(wid * chunk, cnt);
    int e0 = min(b0 + chunk, cnt);

    float4 acc = make_float4(0.f, 0.f, 0.f, 0.f);
    float asum = 0.f;

    int i = b0;
    for (; i + 8 <= e0; i += 8) {
        int   sid[8];
        float w[8];
#pragma unroll
        for (int u = 0; u < 8; u++) sid[u] = __ldg(bk + i + u);   // independent, MLP 8
#pragma unroll
        for (int u = 0; u < 8; u++) w[u] = g_es[sid[u]];          // one dep hop, MLP 8
#pragma unroll
        for (int u = 0; u < 8; u++) {
            float4 p = *reinterpret_cast<const float4*>(&g_P[sid[u] * D + lane * 4]);
            acc.x = fmaf(fmaxf(p.x + qf.x, 0.f), w[u], acc.x);
            acc.y = fmaf(fmaxf(p.y + qf.y, 0.f), w[u], acc.y);
            acc.z = fmaf(fmaxf(p.z + qf.z, 0.f), w[u], acc.z);
            acc.w = fmaf(fmaxf(p.w + qf.w, 0.f), w[u], acc.w);
            asum += w[u];
        }
    }
    for (; i < e0; i++) {
        int   sid = __ldg(bk + i);
        float w   = g_es[sid];
        float4 p  = *reinterpret_cast<const float4*>(&g_P[sid * D + lane * 4]);
        acc.x = fmaf(fmaxf(p.x + qf.x, 0.f), w, acc.x);
        acc.y = fmaf(fmaxf(p.y + qf.y, 0.f), w, acc.y);
        acc.z = fmaf(fmaxf(p.z + qf.z, 0.f), w, acc.z);
        acc.w = fmaf(fmaxf(p.w + qf.w, 0.f), w, acc.w);
        asum += w;
    }

    sacc[half][wid][lane] = acc;
    if (lane == 0) sasum[half][wid] = asum;
    __syncthreads();
    if (t == 0) g_cursor[n] = 0;    // reset for next replay (all reads done)

    const float* sp = reinterpret_cast<const float*>(sacc[half]);
    float a = sp[t] + sp[128 + t] + sp[256 + t] + sp[384 + t];
    float s = sasum[half][0] + sasum[half][1] + sasum[half][2] + sasum[half][3];
    float et = g_et[n];
    out[n * D + t] = (et * a) / (et * s + EPSF);   // exp(s+t)=es*et; EPS outside
}

// ---------------- launch: two graph nodes ----------------
extern "C" void kernel_launch(void* const* d_in, const int* in_sizes, int n_in,
                              void* d_out, int out_size) {
    const float* x   = (const float*)d_in[0];
    const int*   src = (const int*)  d_in[2];
    const int*   tgt = (const int*)  d_in[3];
    const float* fW  = (const float*)d_in[6];
    const float* fb  = (const float*)d_in[7];
    const float* wW  = (const float*)d_in[8];
    float*       out = (float*)d_out;

    // k_pre uses 64KB dynamic smem (+ ~11KB static) -> explicit opt-in required
    static bool attr_done = false;
    if (!attr_done) {
        cudaFuncSetAttribute(k_pre, cudaFuncAttributeMaxDynamicSharedMemorySize,
                             D * D * (int)sizeof(float));
        attr_done = true;
    }

    k_pre<<<256, 256, D * D * sizeof(float)>>>(x, fW, wW, src, tgt);
    k_agg<<<NODES / 2, 256>>>(out, fb);
}